// round 8
// baseline (speedup 1.0000x reference)
#include <cuda_runtime.h>
#include <cuda_bf16.h>
#include <cstdint>

// out[i,m,l] = w1[i,0]*t4[i,(m-1)%56,l] + w1[i,1]*t4[i,(m-2)%56,l]
// t4 as GEMM over input channels j (K=64), one accumulation chain per conv
// tap k (tap = A row shift) and per bf16 hi/lo pass:
//   D[r, i'] += Xsel[p = r + k][j] * w2[ibase+i'][3j+k]
// D rows: 0..55 -> t4[na] (l=r), 64..119 -> t4[nb] (l=r-64); rest discarded.
// mma.sync m16n8k16 bf16 (sm_80 PTX -> compiles for sm_103 base target).
// Grid (ihalf=2, m=56), 256 threads (8 warps), each warp a 32x16 D tile.

static constexpr int A_STRIDE = 144;              // bytes per Xmat row (72 halfs; 36 words ≡ 4 mod 32)
static constexpr int A_BUF    = 132 * A_STRIDE;   // 19008 (hi / lo)
static constexpr int OFF_B    = 2 * A_BUF;        // 38016
static constexpr int B_BUF    = 96 * A_STRIDE;    // 13824 (hi / lo)
static constexpr int SMEM_TOTAL = OFF_B + 2 * B_BUF;  // 65664
static constexpr int STG_STRIDE = 34;             // f32 words, stage overlay

__device__ __forceinline__ void mma_bf16(float* d, const uint32_t* a, const uint32_t* b) {
    asm("mma.sync.aligned.m16n8k16.row.col.f32.bf16.bf16.f32 "
        "{%0,%1,%2,%3}, {%4,%5,%6,%7}, {%8,%9}, {%0,%1,%2,%3};"
        : "+f"(d[0]), "+f"(d[1]), "+f"(d[2]), "+f"(d[3])
        : "r"(a[0]), "r"(a[1]), "r"(a[2]), "r"(a[3]), "r"(b[0]), "r"(b[1]));
}

__device__ __forceinline__ void split_bf16(float v, __nv_bfloat16& hi, __nv_bfloat16& lo) {
    hi = __float2bfloat16(v);
    lo = __float2bfloat16(v - __bfloat162float(hi));
}

__global__ __launch_bounds__(256, 1) void hmma_kernel(
    const float* __restrict__ x,
    const float* __restrict__ w1,
    const float* __restrict__ w2,
    float* __restrict__ out) {

    extern __shared__ char smem[];

    const int tid  = threadIdx.x;
    const int wid  = tid >> 5;
    const int lane = tid & 31;

    const int m     = blockIdx.y;
    const int ihalf = blockIdx.x;
    const int ibase = ihalf * 32;
    const int na    = (m + 55) % 56;
    const int nb    = (m + 54) % 56;

    // ---- Zero filler Xmat rows: {0, 57..63} and {64, 121..131}, both bufs ----
    // 20 rows * 36 words * 2 bufs = 1440 u32 stores.
    for (int idx = tid; idx < 1440; idx += 256) {
        int buf   = idx >= 720;
        int w     = buf ? idx - 720 : idx;
        int rowi  = w / 36;
        int wordi = w % 36;
        int p = (rowi < 8) ? ((rowi == 0) ? 0 : 56 + rowi)
                           : ((rowi == 8) ? 64 : 112 + rowi);
        *reinterpret_cast<uint32_t*>(smem + buf * A_BUF + p * A_STRIDE + wordi * 4) = 0u;
    }

    // ---- Fill Xmat from x: Xmat[sel*64 + 1 + c][j] = x[j, n(sel), c] ----
    for (int idx = tid; idx < 1792; idx += 256) {    // 2 sel * 64 j * 14 float4
        int sel = idx >= 896;
        int qq  = sel ? idx - 896 : idx;
        int j   = qq / 14, c4 = qq % 14;
        int n   = sel ? nb : na;
        float4 v = *reinterpret_cast<const float4*>(&x[(j * 56 + n) * 56 + c4 * 4]);
        int p0 = sel * 64 + 1 + c4 * 4;
        float vv[4] = {v.x, v.y, v.z, v.w};
#pragma unroll
        for (int t = 0; t < 4; ++t) {
            __nv_bfloat16 hi, lo;
            split_bf16(vv[t], hi, lo);
            char* base = smem + (p0 + t) * A_STRIDE + j * 2;
            *reinterpret_cast<__nv_bfloat16*>(base)         = hi;
            *reinterpret_cast<__nv_bfloat16*>(base + A_BUF) = lo;
        }
    }

    // ---- Fill B: Btap[k*32 + i][j] = w2[ibase+i][3j+k], hi/lo ----
    for (int idx = tid; idx < 32 * 192; idx += 256) {
        int i  = idx / 192, jk = idx % 192;
        int j  = jk / 3,    k  = jk % 3;
        __nv_bfloat16 hi, lo;
        split_bf16(w2[(ibase + i) * 192 + jk], hi, lo);
        char* base = smem + OFF_B + (k * 32 + i) * A_STRIDE + j * 2;
        *reinterpret_cast<__nv_bfloat16*>(base)         = hi;
        *reinterpret_cast<__nv_bfloat16*>(base + B_BUF) = lo;
    }
    __syncthreads();

    // ---- Mainloop: 3 passes (hi*hi, hi*lo, lo*hi) x 3 taps x 4 k-steps ----
    const int g  = lane >> 2;      // fragment row group 0..7
    const int q  = lane & 3;       // fragment k group
    const int mt0 = (wid >> 1) * 2;        // m-tiles {mt0, mt0+1}
    const int nblk = (wid & 1) * 16;       // n-col base for this warp's 2 n-tiles

    float d[2][2][4];
#pragma unroll
    for (int a = 0; a < 2; ++a)
#pragma unroll
        for (int b = 0; b < 2; ++b)
#pragma unroll
            for (int c = 0; c < 4; ++c) d[a][b][c] = 0.0f;

    const int aSel[3] = {0, 0, 1};
    const int bSel[3] = {0, 1, 0};

#pragma unroll
    for (int pass = 0; pass < 3; ++pass) {
        const char* ab = smem + aSel[pass] * A_BUF;
        const char* bb = smem + OFF_B + bSel[pass] * B_BUF;
#pragma unroll
        for (int k = 0; k < 3; ++k) {
#pragma unroll
            for (int ks = 0; ks < 4; ++ks) {
                const int akq = ks * 32 + q * 4;
                uint32_t afr[2][4], bfr[2][2];
#pragma unroll
                for (int mtl = 0; mtl < 2; ++mtl) {
                    const char* p = ab + ((mt0 + mtl) * 16 + g + k) * A_STRIDE + akq;
                    afr[mtl][0] = *reinterpret_cast<const uint32_t*>(p);
                    afr[mtl][1] = *reinterpret_cast<const uint32_t*>(p + 8 * A_STRIDE);
                    afr[mtl][2] = *reinterpret_cast<const uint32_t*>(p + 16);
                    afr[mtl][3] = *reinterpret_cast<const uint32_t*>(p + 8 * A_STRIDE + 16);
                }
#pragma unroll
                for (int ntl = 0; ntl < 2; ++ntl) {
                    const char* p = bb + (k * 32 + nblk + ntl * 8 + g) * A_STRIDE + akq;
                    bfr[ntl][0] = *reinterpret_cast<const uint32_t*>(p);
                    bfr[ntl][1] = *reinterpret_cast<const uint32_t*>(p + 16);
                }
#pragma unroll
                for (int mtl = 0; mtl < 2; ++mtl)
#pragma unroll
                    for (int ntl = 0; ntl < 2; ++ntl)
                        mma_bf16(d[mtl][ntl], afr[mtl], bfr[ntl]);
            }
        }
    }

    // ---- Stage D to smem (overlay A-hi buffer), then mix with w1 ----
    __syncthreads();
    float* stg = reinterpret_cast<float*>(smem);   // [128][34] f32 = 17408 B
#pragma unroll
    for (int mtl = 0; mtl < 2; ++mtl) {
#pragma unroll
        for (int ntl = 0; ntl < 2; ++ntl) {
            int r = (mt0 + mtl) * 16 + g;
            int c = nblk + ntl * 8 + 2 * q;
            *reinterpret_cast<float2*>(&stg[r * STG_STRIDE + c]) =
                make_float2(d[mtl][ntl][0], d[mtl][ntl][1]);
            *reinterpret_cast<float2*>(&stg[(r + 8) * STG_STRIDE + c]) =
                make_float2(d[mtl][ntl][2], d[mtl][ntl][3]);
        }
    }
    __syncthreads();

    // out[i,m,l] = w1[i,0]*D[l, ch] + w1[i,1]*D[64+l, ch]
    for (int s = tid; s < 32 * 56; s += 256) {
        int ch = s / 56, l = s % 56;
        int i  = ibase + ch;
        float a = stg[l * STG_STRIDE + ch];
        float b = stg[(64 + l) * STG_STRIDE + ch];
        out[(i * 56 + m) * 56 + l] = fmaf(__ldg(&w1[2 * i]), a, __ldg(&w1[2 * i + 1]) * b);
    }
}

extern "C" void kernel_launch(void* const* d_in, const int* in_sizes, int n_in,
                              void* d_out, int out_size) {
    const float* x  = (const float*)d_in[0];   // (1,64,56,56)
    const float* w1 = (const float*)d_in[1];   // (64,2)
    const float* w2 = (const float*)d_in[2];   // (64,64,3)
    float* out = (float*)d_out;                // (1,64,56,56)

    cudaFuncSetAttribute(hmma_kernel,
                         cudaFuncAttributeMaxDynamicSharedMemorySize, SMEM_TOTAL);

    dim3 grid(2, 56);
    hmma_kernel<<<grid, 256, SMEM_TOTAL>>>(x, w1, w2, out);
}

// round 9
// speedup vs baseline: 1.4337x; 1.4337x over previous
#include <cuda_runtime.h>
#include <cstdint>

// out[i,m,l] = w1[i,0]*t4[i,(m-1)%56,l] + w1[i,1]*t4[i,(m-2)%56,l]
// t4 as GEMM over input channels j (K=64 per conv tap; tap = A row shift):
//   D[r, i'] += Xsel[p = r + tap][j] * w2[ibase+i'][3j+tap]
// D rows 0..55 -> t4[na] (l=r), 64..119 -> t4[nb] (l=r-64); others discarded.
// Single-pass TF32 mma.sync m16n8k8 (fp32 accum). Grid (ihalf=2, m=56),
// 256 threads (8 warps), each warp owns a 32x16 D tile.

static constexpr int A_W     = 68;                   // words per row: (4g+q)%32 perm -> conflict-free frags
static constexpr int A_ROWS  = 132;
static constexpr int OFF_B_W = A_ROWS * A_W;         // 8976 words
static constexpr int B_ROWS  = 96;                   // 3 taps x 32 channels
static constexpr int SMEM_TOTAL = (OFF_B_W + B_ROWS * A_W) * 4;   // 62016 B
static constexpr int STG_STRIDE = 34;                // f32 words, epilogue stage

__device__ __forceinline__ uint32_t f2tf32(float v) {
    uint32_t r; asm("cvt.rna.tf32.f32 %0, %1;" : "=r"(r) : "f"(v)); return r;
}
__device__ __forceinline__ void mma_tf32(float* d, const uint32_t* a, const uint32_t* b) {
    asm("mma.sync.aligned.m16n8k8.row.col.f32.tf32.tf32.f32 "
        "{%0,%1,%2,%3}, {%4,%5,%6,%7}, {%8,%9}, {%0,%1,%2,%3};"
        : "+f"(d[0]), "+f"(d[1]), "+f"(d[2]), "+f"(d[3])
        : "r"(a[0]), "r"(a[1]), "r"(a[2]), "r"(a[3]), "r"(b[0]), "r"(b[1]));
}

__global__ __launch_bounds__(256, 1) void tf32_kernel(
    const float* __restrict__ x,
    const float* __restrict__ w1,
    const float* __restrict__ w2,
    float* __restrict__ out) {

    extern __shared__ uint32_t smem[];
    uint32_t* A = smem;                  // [132 rows][68 w]: A[p][j], tf32 bits
    uint32_t* B = smem + OFF_B_W;        // [96 rows][68 w]: B[tap*32+i][j]

    const int tid  = threadIdx.x;
    const int wid  = tid >> 5;
    const int lane = tid & 31;

    const int m     = blockIdx.y;
    const int ihalf = blockIdx.x;
    const int ibase = ihalf * 32;
    const int na    = (m + 55) % 56;
    const int nb    = (m + 54) % 56;

    // Zero only the halo rows {0, 57, 64, 121}; gap rows feed discarded D rows.
    if (tid < 272) {
        int r = tid / 68, w = tid - r * 68;
        int row = (r == 0) ? 0 : (r == 1) ? 57 : (r == 2) ? 64 : 121;
        A[row * A_W + w] = 0u;
    }

    // Fill A: thread handles (sel, jg, l); loads 4 j-consecutive channels
    // (each LDG.32 coalesced over l across the warp), cvt, one STS.128.
#pragma unroll
    for (int it = 0; it < 7; ++it) {
        int idx = it * 256 + tid;              // 0..1791
        int sel = idx >= 896;
        int rem = idx - sel * 896;
        int jg  = rem / 56;
        int l   = rem - jg * 56;
        int n   = sel ? nb : na;
        int p   = sel * 64 + 1 + l;
        const float* xp = &x[(jg * 4) * 3136 + n * 56 + l];
        uint4 v;
        v.x = f2tf32(xp[0]);
        v.y = f2tf32(xp[3136]);
        v.z = f2tf32(xp[2 * 3136]);
        v.w = f2tf32(xp[3 * 3136]);
        *reinterpret_cast<uint4*>(&A[p * A_W + jg * 4]) = v;
    }

    // Fill B: B[tap*32 + i][j] = tf32(w2[ibase+i][3j+tap]).
#pragma unroll
    for (int it = 0; it < 24; ++it) {
        int idx = it * 256 + tid;              // 0..6143
        int i   = idx / 192;
        int jk  = idx - i * 192;
        int j   = jk / 3;
        int tap = jk - 3 * j;
        B[(tap * 32 + i) * A_W + j] = f2tf32(w2[(ibase + i) * 192 + jk]);
    }
    __syncthreads();

    // ---- Mainloop: 3 taps x 8 k-steps, single tf32 pass ----
    const int g    = lane >> 2;            // 0..7
    const int q    = lane & 3;             // 0..3
    const int mt0  = (wid >> 1) * 2;       // m-tiles {mt0, mt0+1}
    const int nblk = (wid & 1) * 16;       // n base for this warp's 2 n-tiles

    float d[2][2][4];
#pragma unroll
    for (int a = 0; a < 2; ++a)
#pragma unroll
        for (int b = 0; b < 2; ++b)
#pragma unroll
            for (int c = 0; c < 4; ++c) d[a][b][c] = 0.0f;

#pragma unroll
    for (int tap = 0; tap < 3; ++tap) {
#pragma unroll
        for (int ks = 0; ks < 8; ++ks) {
            const int kc = ks * 8 + q;
            uint32_t afr[2][4], bfr[2][2];
#pragma unroll
            for (int mtl = 0; mtl < 2; ++mtl) {
                const int r0 = (mt0 + mtl) * 16 + g + tap;
                const uint32_t* p = &A[r0 * A_W + kc];
                afr[mtl][0] = p[0];
                afr[mtl][1] = p[8 * A_W];
                afr[mtl][2] = p[4];
                afr[mtl][3] = p[8 * A_W + 4];
            }
#pragma unroll
            for (int ntl = 0; ntl < 2; ++ntl) {
                const uint32_t* p = &B[(tap * 32 + nblk + ntl * 8 + g) * A_W + kc];
                bfr[ntl][0] = p[0];
                bfr[ntl][1] = p[4];
            }
#pragma unroll
            for (int mtl = 0; mtl < 2; ++mtl)
#pragma unroll
                for (int ntl = 0; ntl < 2; ++ntl)
                    mma_tf32(d[mtl][ntl], afr[mtl], bfr[ntl]);
        }
    }

    // ---- Stage D (overlay A region), then w1 shift-mix to gmem ----
    __syncthreads();
    float* stg = reinterpret_cast<float*>(smem);   // [128][34] f32
#pragma unroll
    for (int mtl = 0; mtl < 2; ++mtl) {
#pragma unroll
        for (int ntl = 0; ntl < 2; ++ntl) {
            int r = (mt0 + mtl) * 16 + g;
            int c = nblk + ntl * 8 + 2 * q;
            *reinterpret_cast<float2*>(&stg[r * STG_STRIDE + c]) =
                make_float2(d[mtl][ntl][0], d[mtl][ntl][1]);
            *reinterpret_cast<float2*>(&stg[(r + 8) * STG_STRIDE + c]) =
                make_float2(d[mtl][ntl][2], d[mtl][ntl][3]);
        }
    }
    __syncthreads();

    // out[i,m,l] = w1[i,0]*D[l][ch] + w1[i,1]*D[64+l][ch]
#pragma unroll
    for (int it = 0; it < 7; ++it) {
        int s  = it * 256 + tid;               // 0..1791
        int ch = s / 56, l = s - ch * 56;
        int i  = ibase + ch;
        float a = stg[l * STG_STRIDE + ch];
        float b = stg[(64 + l) * STG_STRIDE + ch];
        out[(i * 56 + m) * 56 + l] = fmaf(__ldg(&w1[2 * i]), a, __ldg(&w1[2 * i + 1]) * b);
    }
}

extern "C" void kernel_launch(void* const* d_in, const int* in_sizes, int n_in,
                              void* d_out, int out_size) {
    const float* x  = (const float*)d_in[0];   // (1,64,56,56)
    const float* w1 = (const float*)d_in[1];   // (64,2)
    const float* w2 = (const float*)d_in[2];   // (64,64,3)
    float* out = (float*)d_out;                // (1,64,56,56)

    cudaFuncSetAttribute(tf32_kernel,
                         cudaFuncAttributeMaxDynamicSharedMemorySize, SMEM_TOTAL);

    dim3 grid(2, 56);
    tf32_kernel<<<grid, 256, SMEM_TOTAL>>>(x, w1, w2, out);
}